// round 1
// baseline (speedup 1.0000x reference)
#include <cuda_runtime.h>

#define E_TOTAL 1600000
#define N_NODES 50000

__device__ __forceinline__ void red_add_v4(float* addr, float a, float b, float c, float d) {
    asm volatile("red.global.add.v4.f32 [%0], {%1,%2,%3,%4};"
                 :: "l"(addr), "f"(a), "f"(b), "f"(c), "f"(d) : "memory");
}

__global__ void zero_kernel(float4* __restrict__ out, int n4) {
    int i = blockIdx.x * blockDim.x + threadIdx.x;
    if (i < n4) out[i] = make_float4(0.f, 0.f, 0.f, 0.f);
}

__global__ __launch_bounds__(256) void mp_kernel(
    const float*  __restrict__ node_feats,
    const float4* __restrict__ edge_features,
    const float4* __restrict__ radial,
    const float*  __restrict__ w1,
    const float*  __restrict__ w2,
    const int*    __restrict__ senders,
    const int*    __restrict__ receivers,
    float*        __restrict__ out)
{
    __shared__ float sw1[64];
    __shared__ float sw2[384];
    int tid = threadIdx.x;
    if (tid < 64) sw1[tid] = w1[tid];
    for (int i = tid; i < 384; i += 256) sw2[i] = w2[i];
    __syncthreads();

    int e = blockIdx.x * 256 + tid;
    if (e >= E_TOTAL) return;

    // ---- radial MLP: w = swish(r @ w1) @ w2, with 1/sqrt(32) (+ 1/sqrt(3)) folded in ----
    float4 r0 = radial[2 * e];
    float4 r1 = radial[2 * e + 1];
    float r[8] = {r0.x, r0.y, r0.z, r0.w, r1.x, r1.y, r1.z, r1.w};

    float h[8];
    #pragma unroll
    for (int j = 0; j < 8; j++) {
        float acc = 0.f;
        #pragma unroll
        for (int i = 0; i < 8; i++) acc = fmaf(r[i], sw1[i * 8 + j], acc);
        // swish = x * sigmoid(x)
        h[j] = acc / (1.f + __expf(-acc));
    }

    float w[48];
    #pragma unroll
    for (int c = 0; c < 48; c++) {
        float acc = 0.f;
        #pragma unroll
        for (int j = 0; j < 8; j++) acc = fmaf(h[j], sw2[j * 48 + c], acc);
        w[c] = acc;
    }

    const float SCALE     = 0.17677669529663687f;  // 1/sqrt(32)
    const float INV_SQRT3 = 0.57735026918962576f;  // 1/sqrt(3)
    #pragma unroll
    for (int c = 0; c < 48; c++) w[c] *= SCALE;
    #pragma unroll
    for (int m = 0; m < 8; m++) w[16 + m] *= INV_SQRT3;

    // ---- edge features ----
    float4 ef = edge_features[e];
    float e0  = ef.x;
    float e1a[3] = {ef.y, ef.z, ef.w};

    // ---- node gather ----
    int snd = senders[e];
    int rcv = receivers[e];
    const float4* nf = (const float4*)(node_feats + (size_t)snd * 32);
    float4 n0 = nf[0], n1 = nf[1], n2 = nf[2], n3 = nf[3];
    float4 n4 = nf[4], n5 = nf[5], n6 = nf[6], n7 = nf[7];

    float s[8]  = {n0.x, n0.y, n0.z, n0.w, n1.x, n1.y, n1.z, n1.w};
    float vv[24] = {n2.x, n2.y, n2.z, n2.w, n3.x, n3.y, n3.z, n3.w,
                    n4.x, n4.y, n4.z, n4.w, n5.x, n5.y, n5.z, n5.w,
                    n6.x, n6.y, n6.z, n6.w, n7.x, n7.y, n7.z, n7.w};

    float* outp = out + (size_t)rcv * 96;

    // ---- scalar part: [s*w0:8, s*e0*w8:16, (v.e1)/sqrt3*w16:24] ----
    red_add_v4(outp + 0,  s[0] * w[0], s[1] * w[1], s[2] * w[2], s[3] * w[3]);
    red_add_v4(outp + 4,  s[4] * w[4], s[5] * w[5], s[6] * w[6], s[7] * w[7]);
    red_add_v4(outp + 8,  s[0] * e0 * w[8],  s[1] * e0 * w[9],  s[2] * e0 * w[10], s[3] * e0 * w[11]);
    red_add_v4(outp + 12, s[4] * e0 * w[12], s[5] * e0 * w[13], s[6] * e0 * w[14], s[7] * e0 * w[15]);

    float d[8];
    #pragma unroll
    for (int m = 0; m < 8; m++) {
        d[m] = (vv[3 * m] * e1a[0] + vv[3 * m + 1] * e1a[1] + vv[3 * m + 2] * e1a[2]) * w[16 + m];
    }
    red_add_v4(outp + 16, d[0], d[1], d[2], d[3]);
    red_add_v4(outp + 20, d[4], d[5], d[6], d[7]);

    // ---- vector part: flattened (24,3): [v*w24:32, s⊗e1*w32:40, v*e0*w40:48] ----
    #pragma unroll
    for (int q = 0; q < 18; q++) {
        float t[4];
        #pragma unroll
        for (int u = 0; u < 4; u++) {
            int p  = 4 * q + u;
            int rI = p / 3;
            int k  = p % 3;
            float val;
            if (rI < 8)       val = vv[3 * rI + k] * w[24 + rI];
            else if (rI < 16) val = s[rI - 8] * e1a[k] * w[32 + (rI - 8)];
            else              val = vv[3 * (rI - 16) + k] * e0 * w[40 + (rI - 16)];
            t[u] = val;
        }
        red_add_v4(outp + 24 + 4 * q, t[0], t[1], t[2], t[3]);
    }
}

extern "C" void kernel_launch(void* const* d_in, const int* in_sizes, int n_in,
                              void* d_out, int out_size) {
    const float*  node_feats    = (const float*)d_in[0];
    const float4* edge_features = (const float4*)d_in[1];
    const float4* radial        = (const float4*)d_in[2];
    const float*  w1            = (const float*)d_in[3];
    const float*  w2            = (const float*)d_in[4];
    const int*    senders       = (const int*)d_in[5];
    const int*    receivers     = (const int*)d_in[6];
    float* out = (float*)d_out;

    int n4 = out_size / 4;  // float4 count (out_size = 50000*96)
    zero_kernel<<<(n4 + 255) / 256, 256>>>((float4*)out, n4);

    int blocks = (E_TOTAL + 255) / 256;
    mp_kernel<<<blocks, 256>>>(node_feats, edge_features, radial, w1, w2,
                               senders, receivers, out);
}